// round 5
// baseline (speedup 1.0000x reference)
#include <cuda_runtime.h>

// Problem constants
#define NBINS   256
#define NB      257          // nbins + 1 histogram bins before dropping bin 0
#define CH      3
#define NIMG    32
#define IMG_HW  (512 * 512)
#define ELEMS_PER_IMG (IMG_HW * CH)          // 786432 floats
#define VEC_PER_IMG   (ELEMS_PER_IMG / 4)    // 196608 float4
#define KEYS    (CH * NB)                    // 771 (channel,bin) keys

#define BPI      24          // blocks per image -> grid (24, 32) = 768 CTAs
#define THREADS  256
#define WARPS    (THREADS / 32)

// Global scratch: per-(image,channel,bin) counts. Allocated statically (no cudaMalloc).
__device__ unsigned int g_hist[NIMG * KEYS];

__global__ void zero_hist_kernel() {
    int i = blockIdx.x * blockDim.x + threadIdx.x;
    if (i < NIMG * KEYS) g_hist[i] = 0u;
}

// bin = clip(floor(x / f32(1/257)), 0, 256), matching IEEE division in the reference.
// Fast path: x*257 (error vs exact quotient < ~5e-5 absolute). If within 1e-3 of an
// integer, resolve exactly with a correctly-rounded division (rare: ~0.2% of lanes).
__device__ __forceinline__ int bin_of(float x) {
    const float BW = 1.0f / 257.0f;          // == jnp.float32(1.0/257), > EPS
    float t = x * 257.0f;
    int k = (int)t;                          // t >= 0 -> trunc == floor
    float r = rintf(t);
    if (fabsf(t - r) < 1e-3f) {
        k = (int)floorf(__fdiv_rn(x, BW));   // exact IEEE division, boundary-safe
    }
    return min(max(k, 0), NB - 1);
}

__global__ void __launch_bounds__(THREADS)
hist_kernel(const float* __restrict__ in) {
    __shared__ unsigned int sh[WARPS][KEYS];

    const int b    = blockIdx.y;
    const int tid  = threadIdx.x;
    const int wid  = tid >> 5;
    const int lane = tid & 31;
    unsigned int* h = sh[wid];

    // Zero all warp-private histograms
    for (int i = tid; i < WARPS * KEYS; i += THREADS)
        ((unsigned int*)sh)[i] = 0u;
    __syncthreads();

    const float4* img = (const float4*)(in + (size_t)b * ELEMS_PER_IMG);
    const int stride = BPI * THREADS;        // 6144; 196608 / 6144 = 32 exact iters
    for (int i = blockIdx.x * THREADS + tid; i < VEC_PER_IMG; i += stride) {
        float4 v = img[i];
        int e0 = (4 * i) % 3;                // channel of first element
        int c0 = e0;
        int c1 = c0 + 1; if (c1 == 3) c1 = 0;
        int c2 = c1 + 1; if (c2 == 3) c2 = 0;
        int c3 = c2 + 1; if (c3 == 3) c3 = 0;

        int k0 = c0 * NB + bin_of(v.x);
        int k1 = c1 * NB + bin_of(v.y);
        int k2 = c2 * NB + bin_of(v.z);
        int k3 = c3 * NB + bin_of(v.w);

        // Warp-aggregated, atomic-free accumulation: lanes sharing a key elect a
        // leader; leaders have pairwise-distinct keys -> distinct smem addresses.
        {
            unsigned m = __match_any_sync(0xffffffffu, k0);
            if (lane == (__ffs(m) - 1)) h[k0] += __popc(m);
        }
        {
            unsigned m = __match_any_sync(0xffffffffu, k1);
            if (lane == (__ffs(m) - 1)) h[k1] += __popc(m);
        }
        {
            unsigned m = __match_any_sync(0xffffffffu, k2);
            if (lane == (__ffs(m) - 1)) h[k2] += __popc(m);
        }
        {
            unsigned m = __match_any_sync(0xffffffffu, k3);
            if (lane == (__ffs(m) - 1)) h[k3] += __popc(m);
        }
    }
    __syncthreads();

    // Reduce warp copies, one global atomic per key per block (771 * 768 total).
    for (int i = tid; i < KEYS; i += THREADS) {
        unsigned int s = 0;
        #pragma unroll
        for (int w = 0; w < WARPS; w++) s += sh[w][i];
        if (s) atomicAdd(&g_hist[b * KEYS + i], s);
    }
}

// One block per image: drop bin 0, per-channel normalize, write [B, 256, C].
__global__ void __launch_bounds__(256)
finalize_kernel(float* __restrict__ out) {
    const int b = blockIdx.x;
    const int t = threadIdx.x;               // bin index t -> histogram bin t+1

    __shared__ float wsum[CH][8];
    __shared__ float denom[CH];

    float v[CH];
    #pragma unroll
    for (int c = 0; c < CH; c++)
        v[c] = (float)g_hist[b * KEYS + c * NB + (t + 1)];

    #pragma unroll
    for (int c = 0; c < CH; c++) {
        float s = v[c];
        #pragma unroll
        for (int o = 16; o; o >>= 1) s += __shfl_xor_sync(0xffffffffu, s, o);
        if ((t & 31) == 0) wsum[c][t >> 5] = s;
    }
    __syncthreads();
    if (t < CH) {
        float s = 0.f;
        #pragma unroll
        for (int w = 0; w < 8; w++) s += wsum[t][w];
        denom[t] = fmaxf(s, 1e-7f);
    }
    __syncthreads();

    #pragma unroll
    for (int c = 0; c < CH; c++)
        out[((size_t)b * NBINS + t) * CH + c] = v[c] / denom[c];
}

extern "C" void kernel_launch(void* const* d_in, const int* in_sizes, int n_in,
                              void* d_out, int out_size) {
    const float* in = (const float*)d_in[0];
    float* out = (float*)d_out;

    zero_hist_kernel<<<(NIMG * KEYS + 255) / 256, 256>>>();
    dim3 grid(BPI, NIMG);
    hist_kernel<<<grid, THREADS>>>(in);
    finalize_kernel<<<NIMG, 256>>>(out);
}

// round 6
// speedup vs baseline: 9.3352x; 9.3352x over previous
#include <cuda_runtime.h>

// Problem constants
#define NBINS   256
#define NB      257          // nbins + 1 histogram bins before dropping bin 0
#define CH      3
#define NIMG    32
#define ELEMS_PER_IMG (512 * 512 * CH)       // 786432 floats
#define VEC_PER_IMG   (ELEMS_PER_IMG / 4)    // 196608 float4
#define KEYS    (CH * NB)                    // 771 (channel,bin) keys

#define BPI      36          // blocks per image -> grid (36, 32) = 1152 CTAs (~1 full wave)
#define THREADS  256

// Global scratch: per-(image,channel,bin) counts. Statically allocated; zero at load.
// Invariant: zero on entry to every kernel_launch call (finalize_kernel re-zeros it).
__device__ unsigned int g_hist[NIMG * KEYS];

// bin = clip(floor(RN_f32(x / BW)), 0, 256) with BW = f32(1/257), matching the
// reference's IEEE f32 division exactly (up to ~1e-12-of-midpoint events).
// Double-float trick: inv_hi + inv_lo == 1/(double)BW to 2^-49 relative, so
// fmaf(x, inv_hi, x*inv_lo) carries one final rounding — same as the real division.
__device__ __forceinline__ int bin_of(float x) {
    const double invd   = 1.0 / (double)(1.0f / 257.0f);   // compile-time constant
    const float  inv_hi = (float)invd;
    const float  inv_lo = (float)(invd - (double)inv_hi);
    float q = fmaf(x, inv_hi, x * inv_lo);
    int k = (int)q;                      // q >= 0 -> trunc == floor
    return min(k, NB - 1);               // x<1 can still round up to exactly 257.0
}

__global__ void __launch_bounds__(THREADS)
hist_kernel(const float* __restrict__ in) {
    __shared__ unsigned int sh[KEYS];    // one histogram per CTA, 3084 B

    const int b   = blockIdx.y;
    const int tid = threadIdx.x;

    for (int i = tid; i < KEYS; i += THREADS) sh[i] = 0u;
    __syncthreads();

    // Loop-invariant channel pattern: stride in floats = 36864 ≡ 0 (mod 3).
    const int i0 = blockIdx.x * THREADS + tid;
    const int c0 = (4 * i0) % 3;
    int c1 = c0 + 1; if (c1 == 3) c1 = 0;
    int c2 = c1 + 1; if (c2 == 3) c2 = 0;
    const int k0b = c0 * NB, k1b = c1 * NB, k2b = c2 * NB, k3b = c0 * NB;

    const float4* img = (const float4*)(in + (size_t)b * ELEMS_PER_IMG);
    const int stride = BPI * THREADS;    // 9216 vec4s

    #pragma unroll 4
    for (int i = i0; i < VEC_PER_IMG; i += stride) {
        float4 v = img[i];
        atomicAdd(&sh[k0b + bin_of(v.x)], 1u);
        atomicAdd(&sh[k1b + bin_of(v.y)], 1u);
        atomicAdd(&sh[k2b + bin_of(v.z)], 1u);
        atomicAdd(&sh[k3b + bin_of(v.w)], 1u);
    }
    __syncthreads();

    // One global atomic per key per CTA (771 * 1152 total — trivial).
    unsigned int* gh = &g_hist[b * KEYS];
    for (int i = tid; i < KEYS; i += THREADS) {
        unsigned int s = sh[i];
        if (s) atomicAdd(&gh[i], s);
    }
}

// One block per image: drop bin 0, per-channel normalize, write [B, 256, C].
// Also re-zeros this image's g_hist slice so the next graph replay starts clean.
__global__ void __launch_bounds__(256)
finalize_kernel(float* __restrict__ out) {
    const int b = blockIdx.x;
    const int t = threadIdx.x;               // bin index t -> histogram bin t+1

    __shared__ float wsum[CH][8];
    __shared__ float denom[CH];

    float v[CH];
    #pragma unroll
    for (int c = 0; c < CH; c++)
        v[c] = (float)g_hist[b * KEYS + c * NB + (t + 1)];

    #pragma unroll
    for (int c = 0; c < CH; c++) {
        float s = v[c];
        #pragma unroll
        for (int o = 16; o; o >>= 1) s += __shfl_xor_sync(0xffffffffu, s, o);
        if ((t & 31) == 0) wsum[c][t >> 5] = s;
    }
    __syncthreads();

    // All reads of g_hist completed before the barrier above -> safe to re-zero.
    for (int i = t; i < KEYS; i += 256) g_hist[b * KEYS + i] = 0u;

    if (t < CH) {
        float s = 0.f;
        #pragma unroll
        for (int w = 0; w < 8; w++) s += wsum[t][w];
        denom[t] = fmaxf(s, 1e-7f);
    }
    __syncthreads();

    #pragma unroll
    for (int c = 0; c < CH; c++)
        out[((size_t)b * NBINS + t) * CH + c] = v[c] / denom[c];
}

extern "C" void kernel_launch(void* const* d_in, const int* in_sizes, int n_in,
                              void* d_out, int out_size) {
    const float* in = (const float*)d_in[0];
    float* out = (float*)d_out;

    dim3 grid(BPI, NIMG);
    hist_kernel<<<grid, THREADS>>>(in);
    finalize_kernel<<<NIMG, 256>>>(out);
}